// round 9
// baseline (speedup 1.0000x reference)
#include <cuda_runtime.h>
#include <cstdint>

// Fixed problem shape
#define NB 2048
#define ND 16384
#define NBLK 128                  // persistent blocks (1 per SM, all co-resident)
#define TPB 1024
#define ROWS_B (NB / NBLK)        // 16 rows per block
#define KTOT (ROWS_B * ND / 4 / TPB)   // 64 float4 per thread
#define REG_K 36                  // k <  36 -> registers (rows 0..8)
#define SMEM_K 48                 // k <  48 -> shared    (rows 9..11); else re-read
#define SLAB_F4 (ROWS_B * ND / 4) // 65536 float4 per block slab
#define DATA_F4 ((SMEM_K - REG_K) * TPB)   // 12288 float4 = 192KB smem data

// Scratch (__device__ globals; no allocation allowed)
__device__ float g_psum[NBLK * ND];   // 8MB per-block column partials
__device__ float g_psq [NBLK * ND];   // 8MB
__device__ float g_nmean[ND];
__device__ float g_nvar [ND];
__device__ float g_varpart[4];
__device__ int   g_bar1, g_bar2, g_done;   // zero-init; self-resetting

__device__ __forceinline__ float score_of(float hv, float m, float iv) {
    float d = __fadd_rn(hv, -m);
    return __fmul_rn(__fmul_rn(d, d), iv);
}

__global__ void __launch_bounds__(TPB, 1)
k_fused(const float* __restrict__ h, const float* __restrict__ hmean,
        const float* __restrict__ hvar, float* __restrict__ out) {
    extern __shared__ float4 sh[];   // [0,12288): h rows 9-11; then 4KB scratch
    float* sred = reinterpret_cast<float*>(sh + DATA_F4);
    unsigned long long* wkey = reinterpret_cast<unsigned long long*>(sh + DATA_F4);

    const int b = blockIdx.x;
    const int t = threadIdx.x;
    const float4* hp = reinterpret_cast<const float4*>(h)   + (size_t)b * SLAB_F4 + t;
    float4*       op = reinterpret_cast<float4*>      (out) + (size_t)b * SLAB_F4 + t;

    // ---------------- Phase 1: load slab, partial column stats ----------------
    float4 a[REG_K];
    float4 s[4], q[4];
#pragma unroll
    for (int c = 0; c < 4; ++c) {
        s[c] = make_float4(0.f, 0.f, 0.f, 0.f);
        q[c] = make_float4(0.f, 0.f, 0.f, 0.f);
    }
#pragma unroll
    for (int k = 0; k < KTOT; ++k) {
        // k>=SMEM_K rows get default policy -> L2 retains them for phase 3
        float4 v = (k < SMEM_K) ? __ldcs(&hp[k * TPB]) : hp[k * TPB];
        const int c = k & 3;               // column-group class
        s[c].x += v.x;       s[c].y += v.y;       s[c].z += v.z;       s[c].w += v.w;
        q[c].x += v.x * v.x; q[c].y += v.y * v.y; q[c].z += v.z * v.z; q[c].w += v.w * v.w;
        if (k < REG_K)       a[k] = v;
        else if (k < SMEM_K) sh[(k - REG_K) * TPB + t] = v;
    }
    {
        float4* ps4 = reinterpret_cast<float4*>(g_psum) + (size_t)b * (ND / 4);
        float4* pq4 = reinterpret_cast<float4*>(g_psq)  + (size_t)b * (ND / 4);
#pragma unroll
        for (int c = 0; c < 4; ++c) {
            __stcs(&ps4[c * TPB + t], s[c]);
            __stcs(&pq4[c * TPB + t], q[c]);
        }
    }

    // ---------------- Grid barrier 1 (all 128 blocks co-resident) -------------
    __syncthreads();
    if (t == 0) {
        __threadfence();
        atomicAdd(&g_bar1, 1);
        while (atomicAdd(&g_bar1, 0) < NBLK) {}
        __threadfence();
    }
    __syncthreads();

    // ---------------- Phase 2: finish stats (blocks 0..3 only) ----------------
    if (b < 4) {
        const int col4 = b * TPB + t;      // 0..4095
        float4 ss = make_float4(0.f, 0.f, 0.f, 0.f);
        float4 qq = make_float4(0.f, 0.f, 0.f, 0.f);
        const float4* ps4 = reinterpret_cast<const float4*>(g_psum);
        const float4* pq4 = reinterpret_cast<const float4*>(g_psq);
#pragma unroll 8
        for (int i = 0; i < NBLK; ++i) {
            float4 aa = __ldcs(&ps4[(size_t)i * (ND / 4) + col4]);
            float4 bb = __ldcs(&pq4[(size_t)i * (ND / 4) + col4]);
            ss.x += aa.x; ss.y += aa.y; ss.z += aa.z; ss.w += aa.w;
            qq.x += bb.x; qq.y += bb.y; qq.z += bb.z; qq.w += bb.w;
        }
        const float invB    = 1.0f / (float)NB;
        const float U       = 10.0f;
        const float inv11   = 1.0f / 11.0f;
        const float inv1p1  = 1.0f / 1.1f;
        const float invDen  = 1.0f / (U + 1.0f - invB);
        const float coefOld = U - invB;

        float4 hm = *(reinterpret_cast<const float4*>(hmean) + col4);
        float4 hv = *(reinterpret_cast<const float4*>(hvar)  + col4);

        float4 nm, nv;
        {
            float mu, var, d;
            mu = ss.x * invB; var = qq.x * invB - mu * mu; d = mu - hm.x;
            nv.x = (hv.x * coefOld + var + d * d * inv1p1) * invDen;
            nm.x = (hm.x * U + mu) * inv11;
            mu = ss.y * invB; var = qq.y * invB - mu * mu; d = mu - hm.y;
            nv.y = (hv.y * coefOld + var + d * d * inv1p1) * invDen;
            nm.y = (hm.y * U + mu) * inv11;
            mu = ss.z * invB; var = qq.z * invB - mu * mu; d = mu - hm.z;
            nv.z = (hv.z * coefOld + var + d * d * inv1p1) * invDen;
            nm.z = (hm.z * U + mu) * inv11;
            mu = ss.w * invB; var = qq.w * invB - mu * mu; d = mu - hm.w;
            nv.w = (hv.w * coefOld + var + d * d * inv1p1) * invDen;
            nm.w = (hm.w * U + mu) * inv11;
        }
        reinterpret_cast<float4*>(g_nmean)[col4] = nm;
        reinterpret_cast<float4*>(g_nvar )[col4] = nv;

        sred[t] = nv.x + nv.y + nv.z + nv.w;
        __syncthreads();
        for (int off = 512; off > 0; off >>= 1) {
            if (t < off) sred[t] += sred[t + off];
            __syncthreads();
        }
        if (t == 0) g_varpart[b] = sred[0];
    }

    // ---------------- Grid barrier 2 ----------------
    __syncthreads();
    if (t == 0) {
        __threadfence();
        atomicAdd(&g_bar2, 1);
        while (atomicAdd(&g_bar2, 0) < NBLK) {}
        __threadfence();
    }
    __syncthreads();

    // addend + per-thread mean/inv for this thread's 4 column-groups
    const float addend =
        (g_varpart[0] + g_varpart[1] + g_varpart[2] + g_varpart[3]) / (float)ND * 0.01f;

    float4 m4[4], iv4[4];
    {
        const float4* nm4 = reinterpret_cast<const float4*>(g_nmean);
        const float4* nv4 = reinterpret_cast<const float4*>(g_nvar);
#pragma unroll
        for (int c = 0; c < 4; ++c) {
            m4[c] = __ldg(&nm4[c * TPB + t]);
            float4 nv = __ldg(&nv4[c * TPB + t]);
            iv4[c].x = 1.0f / (nv.x + addend);
            iv4[c].y = 1.0f / (nv.y + addend);
            iv4[c].z = 1.0f / (nv.z + addend);
            iv4[c].w = 1.0f / (nv.w + addend);
        }
    }

    // ---------------- Phase 3: per-row score + write + argmax fixup -----------
    const int lane = t & 31;
    const int warp = t >> 5;

#pragma unroll
    for (int r = 0; r < ROWS_B; ++r) {
        float best = -1.0f;       // scores >= 0
        int   bc   = 0;
        float4 hvv[4];
#pragma unroll
        for (int c = 0; c < 4; ++c) {
            const int k = r * 4 + c;
            float4 v;
            if (k < REG_K)       v = a[k];
            else if (k < SMEM_K) v = sh[(k - REG_K) * TPB + t];
            else                 v = hp[k * TPB];     // L2-resident re-read
            hvv[c] = v;
            __stcs(&op[k * TPB], v);
            float mx = fmaxf(fmaxf(score_of(v.x, m4[c].x, iv4[c].x),
                                   score_of(v.y, m4[c].y, iv4[c].y)),
                             fmaxf(score_of(v.z, m4[c].z, iv4[c].z),
                                   score_of(v.w, m4[c].w, iv4[c].w)));
            if (mx > best) { best = mx; bc = c; }
        }
        // resolve element in winning group (bitwise-identical recompute,
        // first match = lowest column -> jnp.argmax tie semantics)
        int bidx = 0;
#pragma unroll
        for (int c = 0; c < 4; ++c) {
            if (c == bc) {
                float s0 = score_of(hvv[c].x, m4[c].x, iv4[c].x);
                float s1 = score_of(hvv[c].y, m4[c].y, iv4[c].y);
                float s2 = score_of(hvv[c].z, m4[c].z, iv4[c].z);
                bidx = ((c * TPB + t) << 2) +
                       ((s0 == best) ? 0 : (s1 == best) ? 1 : (s2 == best) ? 2 : 3);
            }
        }
        // key = score_bits<<32 | ~col : max => max score, tie => lowest col
        unsigned long long key =
            ((unsigned long long)__float_as_uint(best) << 32) |
            (unsigned long long)(0xFFFFFFFFu - (unsigned)bidx);
#pragma unroll
        for (int off = 16; off > 0; off >>= 1) {
            unsigned long long o = __shfl_xor_sync(0xFFFFFFFFu, key, off);
            if (o > key) key = o;
        }
        if (lane == 0) wkey[warp] = key;
        __syncthreads();               // also orders this row's out-stores
        if (t < 32) {
            unsigned long long k2 = wkey[t];
#pragma unroll
            for (int off = 16; off > 0; off >>= 1) {
                unsigned long long o = __shfl_xor_sync(0xFFFFFFFFu, k2, off);
                if (o > k2) k2 = o;
            }
            if (t == 0) {
                const int w = (int)(0xFFFFFFFFu - (unsigned)(k2 & 0xFFFFFFFFull));
                out[(size_t)(b * ROWS_B + r) * ND + w] = g_nmean[w];
            }
        }
        __syncthreads();               // wkey reuse for next row
    }

    // ---------------- self-reset for graph replay ----------------
    if (t == 0) {
        __threadfence();
        int old = atomicAdd(&g_done, 1);
        if (old == NBLK - 1) {         // everyone is past both barriers
            g_bar1 = 0;
            g_bar2 = 0;
            g_done = 0;
        }
    }
}

// ---------------------------------------------------------------------------
extern "C" void kernel_launch(void* const* d_in, const int* in_sizes, int n_in,
                              void* d_out, int out_size) {
    const float* h     = (const float*)d_in[0];
    const float* hmean = (const float*)d_in[1];
    const float* hvar  = (const float*)d_in[2];
    float* out = (float*)d_out;
    (void)in_sizes; (void)n_in; (void)out_size;

    const int smem_bytes = DATA_F4 * 16 + 4096;   // 192KB data + 4KB scratch
    cudaFuncSetAttribute(k_fused, cudaFuncAttributeMaxDynamicSharedMemorySize,
                         smem_bytes);
    k_fused<<<NBLK, TPB, smem_bytes>>>(h, hmean, hvar, out);
}